// round 2
// baseline (speedup 1.0000x reference)
#include <cuda_runtime.h>
#include <cstddef>

// Problem constants (fixed shapes)
#define N_ROWS 14400      // bs*Q = 16*900
#define N_CLS  91
#define N_TGT  4096
#define T_OUT  4096

#define TPB        128
#define TGT_PER_TH 4
#define TILE_T     (TPB * TGT_PER_TH)   // 512 targets per block
#define TILE_R     32                   // rows per block

// Scratch (no allocations allowed in kernel_launch)
__device__ float  g_cc[N_ROWS * N_CLS];   // 2*(pos-neg) + 2, 5.24 MB
__device__ float4 g_rxyxy[N_ROWS];
__device__ float  g_rarea[N_ROWS];
__device__ float4 g_txyxy[N_TGT];
__device__ float  g_tarea[N_TGT];

// ---------------------------------------------------------------------------
// Prep 1: per (row, class) focal cost table, pre-scaled:
//   table = 2*(pos - neg) + 2
// so main kernel does cost = fma(5, l1, fma(-2, s, table)).
// ---------------------------------------------------------------------------
__global__ void prep_class_kernel(const float* __restrict__ logits) {
    int i = blockIdx.x * blockDim.x + threadIdx.x;
    if (i >= N_ROWS * N_CLS) return;
    float x = logits[i];
    float p = 1.0f / (1.0f + expf(-x));
    float om = 1.0f - p;
    float pos = 0.25f * om * om * (-logf(p + 1e-8f));
    float neg = 0.75f * p * p * (-log1pf(-p + 1e-8f));
    g_cc[i] = 2.0f * (pos - neg) + 2.0f;
}

// ---------------------------------------------------------------------------
// Prep 2: cxcywh -> xyxy + area for pred rows and targets.
// ---------------------------------------------------------------------------
__global__ void prep_boxes_kernel(const float* __restrict__ pboxes,
                                  const float* __restrict__ tboxes) {
    int i = blockIdx.x * blockDim.x + threadIdx.x;
    if (i < N_ROWS) {
        float4 b = ((const float4*)pboxes)[i];
        float x0 = b.x - 0.5f * b.z, y0 = b.y - 0.5f * b.w;
        float x1 = b.x + 0.5f * b.z, y1 = b.y + 0.5f * b.w;
        g_rxyxy[i] = make_float4(x0, y0, x1, y1);
        g_rarea[i] = (x1 - x0) * (y1 - y0);
    }
    if (i < N_TGT) {
        float4 b = ((const float4*)tboxes)[i];
        float x0 = b.x - 0.5f * b.z, y0 = b.y - 0.5f * b.w;
        float x1 = b.x + 0.5f * b.z, y1 = b.y + 0.5f * b.w;
        g_txyxy[i] = make_float4(x0, y0, x1, y1);
        g_tarea[i] = (x1 - x0) * (y1 - y0);
    }
}

__device__ __forceinline__ float rcp_fast(float x) {
    float r;
    asm("rcp.approx.f32 %0, %1;" : "=f"(r) : "f"(x));
    return r;
}

// ---------------------------------------------------------------------------
// Main: block = 512 targets x 32 rows. 128 threads, 4 targets/thread.
// Lanes span targets -> one STG.128 per (thread,row), fully coalesced.
// Row data staged in shared, 12-float records -> 2x LDS.128 + 1x LDS.32.
// ---------------------------------------------------------------------------
__global__ void __launch_bounds__(TPB)
cost_kernel_main(const float* __restrict__ pboxes,
                 const float* __restrict__ tboxes,
                 const int*   __restrict__ tids,
                 float*       __restrict__ out)
{
    __shared__ float s_row[TILE_R][12];   // [0..3]=xyxy [4]=area [5..8]=cxcywh

    const int n0 = blockIdx.y * TILE_R;
    const int t0 = blockIdx.x * TILE_T + threadIdx.x * TGT_PER_TH;

    // Stage 32 rows x 12 floats
    for (int i = threadIdx.x; i < TILE_R * 12; i += TPB) {
        int r = i / 12, f = i - r * 12;
        int n = n0 + r;
        float v = 0.0f;
        if (f < 4)       v = ((const float*)(g_rxyxy + n))[f];
        else if (f == 4) v = g_rarea[n];
        else if (f < 9)  v = pboxes[n * 4 + (f - 5)];
        s_row[r][f] = v;
    }

    // Per-thread target data (4 targets) in registers
    float4 tx[TGT_PER_TH];   // xyxy
    float  ta[TGT_PER_TH];   // area
    float4 tc[TGT_PER_TH];   // cxcywh
    int    cls[TGT_PER_TH];
    #pragma unroll
    for (int j = 0; j < TGT_PER_TH; ++j) {
        int t = t0 + j;
        tx[j]  = g_txyxy[t];
        ta[j]  = g_tarea[t];
        tc[j]  = ((const float4*)tboxes)[t];
        cls[j] = tids[t];
    }

    __syncthreads();

    #pragma unroll 4
    for (int r = 0; r < TILE_R; ++r) {
        const int n = n0 + r;
        const float4 ra = *(const float4*)&s_row[r][0];  // x0 y0 x1 y1
        const float4 rb = *(const float4*)&s_row[r][4];  // area cx cy w
        const float  rh = s_row[r][8];
        const float* __restrict__ ccrow = g_cc + n * N_CLS;

        float c[TGT_PER_TH];
        #pragma unroll
        for (int j = 0; j < TGT_PER_TH; ++j) {
            const float ccv = __ldg(ccrow + cls[j]);     // 2*cc + 2

            // L1 on cxcywh
            float l1 = fabsf(rb.y - tc[j].x) + fabsf(rb.z - tc[j].y)
                     + fabsf(rb.w - tc[j].z) + fabsf(rh   - tc[j].w);

            // intersection (clamped)
            float ltx = fmaxf(ra.x, tx[j].x), lty = fmaxf(ra.y, tx[j].y);
            float rbx = fminf(ra.z, tx[j].z), rby = fminf(ra.w, tx[j].w);
            float iw = fmaxf(rbx - ltx, 0.0f), ih = fmaxf(rby - lty, 0.0f);
            float inter = iw * ih;
            float uni = (rb.x + ta[j]) - inter;

            // enclosing box (no clamp needed: w,h >= 0 for all boxes)
            float ew = fmaxf(ra.z, tx[j].z) - fminf(ra.x, tx[j].x);
            float eh = fmaxf(ra.w, tx[j].w) - fminf(ra.y, tx[j].y);
            float ae = ew * eh;

            // s = inter/uni + uni/ae ; cost = 5*l1 + (2cc+2) - 2*s
            float s = fmaf(uni, rcp_fast(ae), inter * rcp_fast(uni));
            c[j] = fmaf(5.0f, l1, fmaf(-2.0f, s, ccv));
        }
        *(float4*)(out + (size_t)n * T_OUT + t0) =
            make_float4(c[0], c[1], c[2], c[3]);
    }
}

// ---------------------------------------------------------------------------
// Launch
// ---------------------------------------------------------------------------
extern "C" void kernel_launch(void* const* d_in, const int* in_sizes, int n_in,
                              void* d_out, int out_size) {
    const float* logits = (const float*)d_in[0];   // [16,900,91]
    const float* pboxes = (const float*)d_in[1];   // [16,900,4]
    const int*   tids   = (const int*)  d_in[2];   // [4096]
    const float* tboxes = (const float*)d_in[3];   // [4096,4]
    float*       out    = (float*)d_out;           // [16,900,4096]

    {
        int total = N_ROWS * N_CLS;
        prep_class_kernel<<<(total + 255) / 256, 256>>>(logits);
    }
    {
        int total = (N_ROWS > N_TGT ? N_ROWS : N_TGT);
        prep_boxes_kernel<<<(total + 255) / 256, 256>>>(pboxes, tboxes);
    }
    {
        dim3 grid(T_OUT / TILE_T, N_ROWS / TILE_R);
        cost_kernel_main<<<grid, TPB>>>(pboxes, tboxes, tids, out);
    }
}

// round 3
// speedup vs baseline: 1.0730x; 1.0730x over previous
#include <cuda_runtime.h>
#include <cstddef>

// Problem constants (fixed shapes)
#define N_ROWS 14400      // bs*Q = 16*900
#define N_CLS  91
#define N_TGT  4096
#define T_OUT  4096

#define TPB        128
#define TGT_PER_TH 4
#define TILE_T     (TPB * TGT_PER_TH)   // 512 targets per block
#define TILE_R     32                   // rows per block
#define CC_PITCH   92                   // padded shared row pitch

// Scratch (no allocations allowed in kernel_launch)
__device__ float  g_cc[N_ROWS * N_CLS];   // 2*(pos-neg) + 2, 5.24 MB
__device__ float4 g_rxyxy[N_ROWS];
__device__ float  g_rarea[N_ROWS];
__device__ float4 g_txyxy[N_TGT];
__device__ float  g_tarea[N_TGT];

// ---------------------------------------------------------------------------
// Fused prep: class-cost table + box conversion (one launch -> ncu -s 5 lands
// on the main kernel).
//   table = 2*(pos - neg) + 2, cost = fma(5,l1, fma(-2,s, table))
// ---------------------------------------------------------------------------
__global__ void prep_kernel(const float* __restrict__ logits,
                            const float* __restrict__ pboxes,
                            const float* __restrict__ tboxes) {
    int i = blockIdx.x * blockDim.x + threadIdx.x;
    if (i < N_ROWS * N_CLS) {
        float x = logits[i];
        float p = 1.0f / (1.0f + expf(-x));
        float om = 1.0f - p;
        float pos = 0.25f * om * om * (-logf(p + 1e-8f));
        float neg = 0.75f * p * p * (-log1pf(-p + 1e-8f));
        g_cc[i] = 2.0f * (pos - neg) + 2.0f;
    }
    if (i < N_ROWS) {
        float4 b = ((const float4*)pboxes)[i];
        float x0 = b.x - 0.5f * b.z, y0 = b.y - 0.5f * b.w;
        float x1 = b.x + 0.5f * b.z, y1 = b.y + 0.5f * b.w;
        g_rxyxy[i] = make_float4(x0, y0, x1, y1);
        g_rarea[i] = (x1 - x0) * (y1 - y0);
    }
    if (i < N_TGT) {
        float4 b = ((const float4*)tboxes)[i];
        float x0 = b.x - 0.5f * b.z, y0 = b.y - 0.5f * b.w;
        float x1 = b.x + 0.5f * b.z, y1 = b.y + 0.5f * b.w;
        g_txyxy[i] = make_float4(x0, y0, x1, y1);
        g_tarea[i] = (x1 - x0) * (y1 - y0);
    }
}

__device__ __forceinline__ float rcp_fast(float x) {
    float r;
    asm("rcp.approx.f32 %0, %1;" : "=f"(r) : "f"(x));
    return r;
}

// ---------------------------------------------------------------------------
// Main: block = 512 targets x 32 rows. 128 threads, 4 targets/thread.
// cc table for the 32 rows staged in shared (coalesced float4 loads), gathered
// via LDS (~3-way conflicts) instead of scattered LDG (8-12 sectors each).
// ---------------------------------------------------------------------------
__global__ void __launch_bounds__(TPB)
cost_kernel_main(const float* __restrict__ pboxes,
                 const float* __restrict__ tboxes,
                 const int*   __restrict__ tids,
                 float*       __restrict__ out)
{
    __shared__ float s_row[TILE_R][12];            // [0..3]=xyxy [4]=area [5..8]=cxcywh
    __shared__ float s_cc[TILE_R * CC_PITCH];      // class-cost tile, padded pitch

    const int n0 = blockIdx.y * TILE_R;
    const int t0 = blockIdx.x * TILE_T + threadIdx.x * TGT_PER_TH;

    // Stage 32 rows x 12 floats of box data
    for (int i = threadIdx.x; i < TILE_R * 12; i += TPB) {
        int r = i / 12, f = i - r * 12;
        int n = n0 + r;
        float v = 0.0f;
        if (f < 4)       v = ((const float*)(g_rxyxy + n))[f];
        else if (f == 4) v = g_rarea[n];
        else if (f < 9)  v = pboxes[n * 4 + (f - 5)];
        s_row[r][f] = v;
    }

    // Stage cc tile: g_cc[n0*91 .. (n0+32)*91) is contiguous (2912 floats,
    // 16B-aligned since 32*91*4 = 11648 = 728*16). float4 loads, scalar scatter
    // into padded shared rows.
    {
        const float4* __restrict__ src = (const float4*)(g_cc + n0 * N_CLS);
        for (int q = threadIdx.x; q < (TILE_R * N_CLS) / 4; q += TPB) {
            float4 v = src[q];
            int e = q * 4;
            int r = e / N_CLS, c = e - r * N_CLS;
            // elements may straddle a row boundary; compute each explicitly
            #pragma unroll
            for (int k = 0; k < 4; ++k) {
                int rr = r, cc = c + k;
                if (cc >= N_CLS) { rr += 1; cc -= N_CLS; }
                s_cc[rr * CC_PITCH + cc] = ((const float*)&v)[k];
            }
        }
    }

    // Per-thread target data (4 targets) in registers
    float4 tx[TGT_PER_TH];   // xyxy
    float  ta[TGT_PER_TH];   // area
    float4 tc[TGT_PER_TH];   // cxcywh
    int    cls[TGT_PER_TH];
    #pragma unroll
    for (int j = 0; j < TGT_PER_TH; ++j) {
        int t = t0 + j;
        tx[j]  = g_txyxy[t];
        ta[j]  = g_tarea[t];
        tc[j]  = ((const float4*)tboxes)[t];
        cls[j] = tids[t];
    }

    __syncthreads();

    #pragma unroll 4
    for (int r = 0; r < TILE_R; ++r) {
        const int n = n0 + r;
        const float4 ra = *(const float4*)&s_row[r][0];  // x0 y0 x1 y1
        const float4 rb = *(const float4*)&s_row[r][4];  // area cx cy w
        const float  rh = s_row[r][8];
        const float* __restrict__ ccrow = s_cc + r * CC_PITCH;

        float c[TGT_PER_TH];
        #pragma unroll
        for (int j = 0; j < TGT_PER_TH; ++j) {
            const float ccv = ccrow[cls[j]];             // 2*cc + 2 (shared)

            // L1 on cxcywh
            float l1 = fabsf(rb.y - tc[j].x) + fabsf(rb.z - tc[j].y)
                     + fabsf(rb.w - tc[j].z) + fabsf(rh   - tc[j].w);

            // intersection (clamped)
            float ltx = fmaxf(ra.x, tx[j].x), lty = fmaxf(ra.y, tx[j].y);
            float rbx = fminf(ra.z, tx[j].z), rby = fminf(ra.w, tx[j].w);
            float iw = fmaxf(rbx - ltx, 0.0f), ih = fmaxf(rby - lty, 0.0f);
            float inter = iw * ih;
            float uni = (rb.x + ta[j]) - inter;

            // enclosing box (no clamp needed: w,h >= 0 for all boxes)
            float ew = fmaxf(ra.z, tx[j].z) - fminf(ra.x, tx[j].x);
            float eh = fmaxf(ra.w, tx[j].w) - fminf(ra.y, tx[j].y);
            float ae = ew * eh;

            // s = inter/uni + uni/ae ; cost = 5*l1 + (2cc+2) - 2*s
            float s = fmaf(uni, rcp_fast(ae), inter * rcp_fast(uni));
            c[j] = fmaf(5.0f, l1, fmaf(-2.0f, s, ccv));
        }
        *(float4*)(out + (size_t)n * T_OUT + t0) =
            make_float4(c[0], c[1], c[2], c[3]);
    }
}

// ---------------------------------------------------------------------------
// Launch
// ---------------------------------------------------------------------------
extern "C" void kernel_launch(void* const* d_in, const int* in_sizes, int n_in,
                              void* d_out, int out_size) {
    const float* logits = (const float*)d_in[0];   // [16,900,91]
    const float* pboxes = (const float*)d_in[1];   // [16,900,4]
    const int*   tids   = (const int*)  d_in[2];   // [4096]
    const float* tboxes = (const float*)d_in[3];   // [4096,4]
    float*       out    = (float*)d_out;           // [16,900,4096]

    {
        int total = N_ROWS * N_CLS;
        prep_kernel<<<(total + 255) / 256, 256>>>(logits, pboxes, tboxes);
    }
    {
        dim3 grid(T_OUT / TILE_T, N_ROWS / TILE_R);
        cost_kernel_main<<<grid, TPB>>>(pboxes, tboxes, tids, out);
    }
}